// round 2
// baseline (speedup 1.0000x reference)
#include <cuda_runtime.h>

#define TB      256     // threads per block == samples per block
#define NN      64      // input dim
#define HH      256     // hidden dim
#define OO      64      // output dim
#define MAXIT   30
#define TOLV    1e-7f

#define SXS     65      // x/out staging tile row stride (bank-conflict pad)

// smem layout (floats):
//   sx   : TB*SXS   = 16640   (x staging, reused for output staging)
//   sw1  : HH*NN    = 16384   (row-major, row j = 64 floats)
//   sw2t : HH*OO    = 16384   (transposed: [j][k])
//   sc2  : NN (=-2r)  srr : NN (r)   sb1 : HH   sb2 : OO
#define SMEM_FLOATS (TB*SXS + HH*NN + HH*OO + NN + NN + HH + OO)

typedef unsigned long long u64;

__device__ __forceinline__ u64 ffma2(u64 a, u64 b, u64 c) {
    u64 d;
    asm("fma.rn.f32x2 %0, %1, %2, %3;" : "=l"(d) : "l"(a), "l"(b), "l"(c));
    return d;
}
__device__ __forceinline__ u64 pack2(float lo, float hi) {
    u64 d;
    asm("mov.b64 %0, {%1, %2};" : "=l"(d) : "f"(lo), "f"(hi));
    return d;
}
__device__ __forceinline__ void unpack2(float& lo, float& hi, u64 v) {
    asm("mov.b64 {%0, %1}, %2;" : "=f"(lo), "=f"(hi) : "l"(v));
}

__global__ __launch_bounds__(TB, 1)
void aniso_kernel(const float* __restrict__ x,  const float* __restrict__ r,
                  const float* __restrict__ W1, const float* __restrict__ b1,
                  const float* __restrict__ W2, const float* __restrict__ b2,
                  float* __restrict__ out)
{
    extern __shared__ float sm[];
    float* sx   = sm;
    float* sw1  = sx   + TB * SXS;
    float* sw2t = sw1  + HH * NN;
    float* sc2  = sw2t + HH * OO;
    float* srr  = sc2  + NN;
    float* sb1  = srr  + NN;
    float* sb2  = sb1  + HH;

    const int tid = threadIdx.x;
    const long long b0 = (long long)blockIdx.x * TB;

    // ---- stage weights / constants ----
    for (int idx = tid; idx < HH * NN; idx += TB) sw1[idx] = W1[idx];
    for (int idx = tid; idx < OO * HH; idx += TB) {
        int k = idx >> 8;        // output index (row of W2)
        int j = idx & 255;       // hidden index
        sw2t[j * OO + k] = W2[idx];
    }
    if (tid < NN) { float rv = r[tid]; srr[tid] = rv; sc2[tid] = -2.0f * rv; }
    for (int idx = tid; idx < HH; idx += TB) sb1[idx] = b1[idx];
    if (tid < OO) sb2[tid] = b2[tid];

    // ---- stage x tile (coalesced) ----
    const float* xg = x + b0 * NN;
    for (int idx = tid; idx < TB * NN; idx += TB) {
        int rr = idx >> 6, cc = idx & 63;
        sx[rr * SXS + cc] = xg[idx];
    }
    __syncthreads();

    // ---- per-thread Newton solve (log-domain) of sum_i e^{-2 r_i s} x_i^2 = 1 ----
    float xsq[NN];
    #pragma unroll
    for (int i = 0; i < NN; i++) {
        float v = sx[tid * SXS + i];
        xsq[i] = v * v;
    }

    float s = 0.0f;
    #pragma unroll 1
    for (int it = 0; it < MAXIT; it++) {
        float f0 = 0.0f, f1 = 0.0f;       // F(s) split accumulators
        float g0 = 0.0f, g1 = 0.0f;       // F'(s) split accumulators
        #pragma unroll
        for (int i = 0; i < NN; i += 2) {
            float c0 = sc2[i],       c1 = sc2[i + 1];
            float e0 = __expf(c0 * s), e1 = __expf(c1 * s);
            float p0 = e0 * xsq[i],    p1 = e1 * xsq[i + 1];
            f0 += p0;                  f1 += p1;
            g0 = fmaf(c0, p0, g0);     g1 = fmaf(c1, p1, g1);
        }
        float F = f0 + f1;
        float G = g0 + g1;
        if (F < 1e-30f || G == 0.0f) break;        // all-zero row -> s stays 0
        if (fabsf(F - 1.0f) < TOLV) break;         // converged (same rule as ref)
        // Newton on ln F: exactly linear when all r equal -> ~3-4 iters
        s -= __logf(F) * F / G;
    }

    // ---- x_sphere (packed pairs over i) and output scale ----
    u64 xvp[NN / 2];
    #pragma unroll
    for (int i = 0; i < NN; i += 2) {
        float v0 = sx[tid * SXS + i]     * __expf(-srr[i]     * s);
        float v1 = sx[tid * SXS + i + 1] * __expf(-srr[i + 1] * s);
        xvp[i >> 1] = pack2(v0, v1);
    }
    const float escale = __expf(s);     // NU = 1

    // ---- fused MLP with packed f32x2 FMA ----
    u64 accp[OO / 2];
    #pragma unroll
    for (int kp = 0; kp < OO / 2; kp++)
        accp[kp] = pack2(sb2[2 * kp], sb2[2 * kp + 1]);

    #pragma unroll 1
    for (int j = 0; j < HH; j += 4) {
        // layer 1: 4 hidden units, pair over i
        u64 q0 = 0ull, q1 = 0ull, q2 = 0ull, q3 = 0ull;
        const ulonglong2* r0 = (const ulonglong2*)(sw1 + (j + 0) * NN);
        const ulonglong2* r1 = (const ulonglong2*)(sw1 + (j + 1) * NN);
        const ulonglong2* r2 = (const ulonglong2*)(sw1 + (j + 2) * NN);
        const ulonglong2* r3 = (const ulonglong2*)(sw1 + (j + 3) * NN);
        #pragma unroll
        for (int t = 0; t < NN / 4; t++) {          // 16 iters, 4x LDS.128 each
            ulonglong2 a = r0[t], b = r1[t], c = r2[t], d = r3[t];
            u64 xa = xvp[2 * t], xb = xvp[2 * t + 1];
            q0 = ffma2(a.x, xa, q0); q0 = ffma2(a.y, xb, q0);
            q1 = ffma2(b.x, xa, q1); q1 = ffma2(b.y, xb, q1);
            q2 = ffma2(c.x, xa, q2); q2 = ffma2(c.y, xb, q2);
            q3 = ffma2(d.x, xa, q3); q3 = ffma2(d.y, xb, q3);
        }
        float l0, u0, l1, u1, l2, u2, l3, u3;
        unpack2(l0, u0, q0); unpack2(l1, u1, q1);
        unpack2(l2, u2, q2); unpack2(l3, u3, q3);
        float h0 = fmaxf(l0 + u0 + sb1[j + 0], 0.0f);
        float h1 = fmaxf(l1 + u1 + sb1[j + 1], 0.0f);
        float h2 = fmaxf(l2 + u2 + sb1[j + 2], 0.0f);
        float h3 = fmaxf(l3 + u3 + sb1[j + 3], 0.0f);

        // layer 2: pair over k, broadcast h into both lanes
        u64 hp0 = pack2(h0, h0), hp1 = pack2(h1, h1);
        u64 hp2 = pack2(h2, h2), hp3 = pack2(h3, h3);
        const ulonglong2* v0 = (const ulonglong2*)(sw2t + (j + 0) * OO);
        const ulonglong2* v1 = (const ulonglong2*)(sw2t + (j + 1) * OO);
        const ulonglong2* v2 = (const ulonglong2*)(sw2t + (j + 2) * OO);
        const ulonglong2* v3 = (const ulonglong2*)(sw2t + (j + 3) * OO);
        #pragma unroll
        for (int t = 0; t < OO / 4; t++) {          // 16 iters, 4x LDS.128 each
            ulonglong2 a = v0[t], b = v1[t], c = v2[t], d = v3[t];
            u64 e0 = accp[2 * t], e1 = accp[2 * t + 1];
            e0 = ffma2(a.x, hp0, e0); e1 = ffma2(a.y, hp0, e1);
            e0 = ffma2(b.x, hp1, e0); e1 = ffma2(b.y, hp1, e1);
            e0 = ffma2(c.x, hp2, e0); e1 = ffma2(c.y, hp2, e1);
            e0 = ffma2(d.x, hp3, e0); e1 = ffma2(d.y, hp3, e1);
            accp[2 * t] = e0; accp[2 * t + 1] = e1;
        }
    }

    // ---- stage outputs to smem (reuse sx), then coalesced store ----
    __syncthreads();   // everyone done reading sx
    #pragma unroll
    for (int kp = 0; kp < OO / 2; kp++) {
        float lo, hi;
        unpack2(lo, hi, accp[kp]);
        sx[tid * SXS + 2 * kp]     = lo * escale;
        sx[tid * SXS + 2 * kp + 1] = hi * escale;
    }
    __syncthreads();

    float* og = out + b0 * OO;
    for (int idx = tid; idx < TB * OO; idx += TB) {
        int rr = idx >> 6, cc = idx & 63;
        og[idx] = sx[rr * SXS + cc];
    }
}

extern "C" void kernel_launch(void* const* d_in, const int* in_sizes, int n_in,
                              void* d_out, int out_size)
{
    const float* x  = (const float*)d_in[0];
    const float* r  = (const float*)d_in[1];
    const float* W1 = (const float*)d_in[2];
    const float* b1 = (const float*)d_in[3];
    const float* W2 = (const float*)d_in[4];
    const float* b2 = (const float*)d_in[5];
    float* out = (float*)d_out;

    const int B = in_sizes[0] / NN;          // 262144
    const size_t smem = SMEM_FLOATS * sizeof(float);   // ~195 KB

    cudaFuncSetAttribute(aniso_kernel,
                         cudaFuncAttributeMaxDynamicSharedMemorySize, (int)smem);
    aniso_kernel<<<B / TB, TB, smem>>>(x, r, W1, b1, W2, b2, out);
}

// round 5
// speedup vs baseline: 1.9335x; 1.9335x over previous
#include <cuda_runtime.h>
#include <cuda_bf16.h>
#include <cstdint>

#define NN      64
#define HH      256
#define OO      64
#define MAXIT   30
#define TOLV    1e-7f

#define TB      256          // 8 warps
#define ROWS    128          // samples per block (16 per warp)

// ---- smem byte layout (padded strides for conflict-free fragment LDS) ----
// Xs  : [128 rows][72 bf16]  hi/lo      (stride 144B; word stride 36 ≡ 4 mod 32)
// W1  : [256 rows][72 bf16]  hi/lo      (row n = W1[n][0..63])
// W2  : [64 rows][264 bf16]  hi/lo      (row n = W2[n][0..255]; stride 528B, 132 ≡ 4)
#define SM_XH   0
#define SM_XL   (SM_XH + ROWS*144)        // 18432
#define SM_W1H  (SM_XL + ROWS*144)        // 36864
#define SM_W1L  (SM_W1H + 256*144)        // 73728
#define SM_W2H  (SM_W1L + 256*144)        // 110592
#define SM_W2L  (SM_W2H + 64*528)         // 144384
#define SM_RR   (SM_W2L + 64*528)         // 178176  r[64] f32
#define SM_B1   (SM_RR + 256)             // 178432  b1[256] f32
#define SM_B2   (SM_B1 + 1024)            // 179456  b2[64] f32
#define SM_ES   (SM_B2 + 256)             // 179712  es[128] f32
#define SM_TOTAL (SM_ES + 512)            // 180224 bytes (~176 KB)

// pack two f32 -> bf16x2 (arg0 -> low half, arg1 -> high half)
__device__ __forceinline__ uint32_t pack_bf16x2(float lo, float hi) {
    uint32_t d;
    asm("cvt.rn.bf16x2.f32 %0, %1, %2;" : "=r"(d) : "f"(hi), "f"(lo));
    return d;
}
// split packed bf16x2 back into the two f32 "hi" values
__device__ __forceinline__ void bf2_vals(uint32_t p, float& v0, float& v1) {
    v0 = __uint_as_float(p << 16);
    v1 = __uint_as_float(p & 0xffff0000u);
}
// hi/lo split of a pair
__device__ __forceinline__ void split2(float v0, float v1, uint32_t& hi, uint32_t& lo) {
    hi = pack_bf16x2(v0, v1);
    float h0, h1; bf2_vals(hi, h0, h1);
    lo = pack_bf16x2(v0 - h0, v1 - h1);
}

__device__ __forceinline__ void mma16816(float* c, const uint32_t* a, uint32_t b0, uint32_t b1) {
    asm volatile("mma.sync.aligned.m16n8k16.row.col.f32.bf16.bf16.f32 "
                 "{%0,%1,%2,%3}, {%4,%5,%6,%7}, {%8,%9}, {%0,%1,%2,%3};"
                 : "+f"(c[0]), "+f"(c[1]), "+f"(c[2]), "+f"(c[3])
                 : "r"(a[0]), "r"(a[1]), "r"(a[2]), "r"(a[3]), "r"(b0), "r"(b1));
}

__global__ __launch_bounds__(TB, 1)
void aniso_hmma_kernel(const float* __restrict__ x,  const float* __restrict__ r,
                       const float* __restrict__ W1, const float* __restrict__ b1,
                       const float* __restrict__ W2, const float* __restrict__ b2,
                       float* __restrict__ out)
{
    extern __shared__ char sm[];
    float* srr = (float*)(sm + SM_RR);
    float* sb1 = (float*)(sm + SM_B1);
    float* sb2 = (float*)(sm + SM_B2);
    float* ses = (float*)(sm + SM_ES);

    const int tid  = threadIdx.x;
    const int wid  = tid >> 5;
    const int lane = tid & 31;
    const int g    = lane >> 2;      // fragment group row
    const int t    = lane & 3;       // thread-in-group
    const size_t b0 = (size_t)blockIdx.x * ROWS;

    // ---- stage constants ----
    if (tid < NN) { srr[tid] = r[tid]; sb2[tid] = b2[tid]; }
    sb1[tid] = b1[tid];   // TB == HH == 256

    // ---- W1 -> bf16 hi/lo, [256][72] padded rows ----
    #pragma unroll 4
    for (int p = tid; p < HH * NN / 2; p += TB) {
        int h  = p >> 5;
        int n2 = (p & 31) * 2;
        float2 w = *(const float2*)(W1 + h * NN + n2);
        uint32_t hi, lo; split2(w.x, w.y, hi, lo);
        *(uint32_t*)(sm + SM_W1H + h * 144 + n2 * 2) = hi;
        *(uint32_t*)(sm + SM_W1L + h * 144 + n2 * 2) = lo;
    }
    // ---- W2 -> bf16 hi/lo, [64][264] padded rows ----
    #pragma unroll 4
    for (int p = tid; p < OO * HH / 2; p += TB) {
        int o  = p >> 7;
        int k2 = (p & 127) * 2;
        float2 w = *(const float2*)(W2 + o * HH + k2);
        uint32_t hi, lo; split2(w.x, w.y, hi, lo);
        *(uint32_t*)(sm + SM_W2H + o * 528 + k2 * 2) = hi;
        *(uint32_t*)(sm + SM_W2L + o * 528 + k2 * 2) = lo;
    }

    // ---- Newton solve + x_sphere conversion (threads 0..127, one row each) ----
    if (tid < ROWS) {
        float xv[NN];
        const float4* xr = (const float4*)(x + (b0 + tid) * NN);
        #pragma unroll
        for (int i = 0; i < NN / 4; i++) {
            float4 v = xr[i];
            xv[4*i] = v.x; xv[4*i+1] = v.y; xv[4*i+2] = v.z; xv[4*i+3] = v.w;
        }
        float s = 0.0f;
        #pragma unroll 1
        for (int it = 0; it < MAXIT; it++) {
            float m2s = -2.0f * s;
            float f0 = 0.0f, f1 = 0.0f, g0 = 0.0f, g1 = 0.0f;
            #pragma unroll
            for (int i = 0; i < NN; i += 2) {
                float r0 = srr[i], r1 = srr[i+1];
                float e0 = __expf(r0 * m2s), e1 = __expf(r1 * m2s);
                float p0 = e0 * xv[i] * xv[i], p1 = e1 * xv[i+1] * xv[i+1];
                f0 += p0;              f1 += p1;
                g0 = fmaf(r0, p0, g0); g1 = fmaf(r1, p1, g1);
            }
            float F = f0 + f1;
            float G = -2.0f * (g0 + g1);
            if (F < 1e-30f || G == 0.0f) break;       // all-zero row -> s = 0
            if (fabsf(F - 1.0f) < TOLV) break;        // same stop rule as ref
            s -= __logf(F) * F / G;                   // Newton on ln F (monotone)
        }
        ses[tid] = __expf(s);                         // NU = 1
        // x_sphere bf16 hi/lo
        #pragma unroll
        for (int i = 0; i < NN; i += 2) {
            float v0 = xv[i]   * __expf(-srr[i]   * s);
            float v1 = xv[i+1] * __expf(-srr[i+1] * s);
            uint32_t hi, lo; split2(v0, v1, hi, lo);
            *(uint32_t*)(sm + SM_XH + tid * 144 + i * 2) = hi;
            *(uint32_t*)(sm + SM_XL + tid * 144 + i * 2) = lo;
        }
    }
    __syncthreads();

    // ---- mainloop: per-warp 16-row tile, hidden processed in 4 chunks of 64 ----
    const int rowb = wid * 16;
    const char* XH = sm + SM_XH + (rowb + g) * 144;
    const char* XL = sm + SM_XL + (rowb + g) * 144;

    float C2[8][4];
    #pragma unroll
    for (int nt = 0; nt < 8; nt++)
        { C2[nt][0] = 0.f; C2[nt][1] = 0.f; C2[nt][2] = 0.f; C2[nt][3] = 0.f; }

    #pragma unroll 1
    for (int hc = 0; hc < 4; hc++) {
        // ===== layer 1 chunk: C1[16 x 64] = Xs[16x64] @ W1^T[:, hc*64..] =====
        float C1[8][4];
        #pragma unroll
        for (int nt = 0; nt < 8; nt++)
            { C1[nt][0] = 0.f; C1[nt][1] = 0.f; C1[nt][2] = 0.f; C1[nt][3] = 0.f; }

        #pragma unroll
        for (int ks = 0; ks < 4; ks++) {
            const int kb = (ks * 16 + t * 2) * 2;   // byte offset of k-pair
            uint32_t ah[4], al[4];
            ah[0] = *(const uint32_t*)(XH + kb);
            ah[1] = *(const uint32_t*)(XH + 8 * 144 + kb);
            ah[2] = *(const uint32_t*)(XH + kb + 16);
            ah[3] = *(const uint32_t*)(XH + 8 * 144 + kb + 16);
            al[0] = *(const uint32_t*)(XL + kb);
            al[1] = *(const uint32_t*)(XL + 8 * 144 + kb);
            al[2] = *(const uint32_t*)(XL + kb + 16);
            al[3] = *(const uint32_t*)(XL + 8 * 144 + kb + 16);
            #pragma unroll
            for (int nt = 0; nt < 8; nt++) {
                const int n = hc * 64 + nt * 8 + g;
                uint32_t bh0 = *(const uint32_t*)(sm + SM_W1H + n * 144 + kb);
                uint32_t bh1 = *(const uint32_t*)(sm + SM_W1H + n * 144 + kb + 16);
                uint32_t bl0 = *(const uint32_t*)(sm + SM_W1L + n * 144 + kb);
                uint32_t bl1 = *(const uint32_t*)(sm + SM_W1L + n * 144 + kb + 16);
                mma16816(C1[nt], ah, bh0, bh1);
                mma16816(C1[nt], ah, bl0, bl1);
                mma16816(C1[nt], al, bh0, bh1);
            }
        }

        // ===== epilogue 1 (registers only): +b1, relu, bf16 split -> A2 frags =====
        uint32_t a2h[4][4], a2l[4][4];
        #pragma unroll
        for (int nt = 0; nt < 8; nt++) {
            const int colb = hc * 64 + nt * 8 + t * 2;
            float bb0 = sb1[colb], bb1 = sb1[colb + 1];
            float v0 = fmaxf(C1[nt][0] + bb0, 0.0f);
            float v1 = fmaxf(C1[nt][1] + bb1, 0.0f);
            float v2 = fmaxf(C1[nt][2] + bb0, 0.0f);
            float v3 = fmaxf(C1[nt][3] + bb1, 0.0f);
            const int ks = nt >> 1, q = (nt & 1) * 2;
            split2(v0, v1, a2h[ks][q],     a2l[ks][q]);
            split2(v2, v3, a2h[ks][q + 1], a2l[ks][q + 1]);
        }

        // ===== layer 2 chunk: C2 += H[16 x 64] @ W2^T[hc*64.., :] =====
        #pragma unroll
        for (int ks = 0; ks < 4; ks++) {
            const int kb = (hc * 64 + ks * 16 + t * 2) * 2;
            #pragma unroll
            for (int nt = 0; nt < 8; nt++) {
                const int n = nt * 8 + g;
                uint32_t bh0 = *(const uint32_t*)(sm + SM_W2H + n * 528 + kb);
                uint32_t bh1 = *(const uint32_t*)(sm + SM_W2H + n * 528 + kb + 16);
                uint32_t bl0 = *(const uint32_t*)(sm + SM_W2L + n * 528 + kb);
                uint32_t bl1 = *(const uint32_t*)(sm + SM_W2L + n * 528 + kb + 16);
                mma16816(C2[nt], a2h[ks], bh0, bh1);
                mma16816(C2[nt], a2h[ks], bl0, bl1);
                mma16816(C2[nt], a2l[ks], bh0, bh1);
            }
        }
    }

    // ---- epilogue 2: (+b2) * e^s, float2 stores ----
    const float es0 = ses[rowb + g];
    const float es1 = ses[rowb + g + 8];
    float* o0r = out + (b0 + rowb + g) * OO;
    float* o1r = out + (b0 + rowb + g + 8) * OO;
    #pragma unroll
    for (int nt = 0; nt < 8; nt++) {
        const int col = nt * 8 + t * 2;
        float bb0 = sb2[col], bb1 = sb2[col + 1];
        float2 u0, u1;
        u0.x = (C2[nt][0] + bb0) * es0;  u0.y = (C2[nt][1] + bb1) * es0;
        u1.x = (C2[nt][2] + bb0) * es1;  u1.y = (C2[nt][3] + bb1) * es1;
        *(float2*)(o0r + col) = u0;
        *(float2*)(o1r + col) = u1;
    }
}

extern "C" void kernel_launch(void* const* d_in, const int* in_sizes, int n_in,
                              void* d_out, int out_size)
{
    const float* x  = (const float*)d_in[0];
    const float* r  = (const float*)d_in[1];
    const float* W1 = (const float*)d_in[2];
    const float* b1 = (const float*)d_in[3];
    const float* W2 = (const float*)d_in[4];
    const float* b2 = (const float*)d_in[5];
    float* out = (float*)d_out;

    const int B = in_sizes[0] / NN;          // 262144
    cudaFuncSetAttribute(aniso_hmma_kernel,
                         cudaFuncAttributeMaxDynamicSharedMemorySize, SM_TOTAL);
    aniso_hmma_kernel<<<B / ROWS, TB, SM_TOTAL>>>(x, r, W1, b1, W2, b2, out);
}